// round 15
// baseline (speedup 1.0000x reference)
#include <cuda_runtime.h>
#include <cuda_fp16.h>
#include <math.h>

#define MAX_B    512
#define MAX_HALF 50048
#define CPR      16          // chunk CTAs per row
#define NT       256         // threads per CTA
#define GS       16          // pooled values per group (one hot iteration)

// Pooled rows scratch in fp16 (51 MB) — written pass1, read pass2; L2-friendly.
__device__ __half g_pool[(size_t)MAX_B * MAX_HALF];
// Per-(row,chunk) partial moments {sum, sumsq}
__device__ float2 g_part[MAX_B * CPR];

// Pass 1: stream x (ldcs) + noise (L2-resident), pooled fp16 -> g_pool,
// partial (sum,sumsq) per chunk -> g_part.  16 pooled per hot iteration.
__global__ __launch_bounds__(NT)
void pass1_kernel(const float* __restrict__ x,
                  const float* __restrict__ noise,
                  const int*   __restrict__ move_p,
                  int L) {
    const int halfL   = L >> 1;
    const int ngroups = halfL / GS;
    const int gpc     = (ngroups + CPR - 1) / CPR;
    const int row     = blockIdx.x / CPR;
    const int c       = blockIdx.x % CPR;
    const int gc_lo   = c * gpc;
    const int gc_hi   = min(gc_lo + gpc, ngroups);
    const int tid     = threadIdx.x;

    const float* __restrict__ xrow = x + (size_t)row * (size_t)L;
    __half*      __restrict__ prow = g_pool + (size_t)row * (size_t)halfL;

    int mv = __ldg(move_p);
    mv %= L; if (mv < 0) mv += L;

    // Fast-path interval in group space: s0 = 2*GS*g - mv needs
    // s0 >= 0, s0 + 2*GS - 1 < L, and 16B alignment (mv % 4 == 0).
    int fl, fh;
    if ((mv & 3) == 0) {
        fl = (mv + 2 * GS - 1) / (2 * GS);        if (fl > ngroups) fl = ngroups;
        fh = (L + mv - 2 * GS) / (2 * GS) + 1;    if (fh > ngroups) fh = ngroups;
        if (fh < fl) fh = fl;
    } else { fl = 0; fh = 0; }

    int lo = max(gc_lo, fl); if (lo > gc_hi) lo = gc_hi;
    int hi = min(gc_hi, fh); if (hi < lo)    hi = lo;

    float sum = 0.0f, sumsq = 0.0f;

    // ---- scalar edge groups (wrap region) ----
    const int n_low = lo - gc_lo, n_high = gc_hi - hi;
    for (int e = tid; e < n_low + n_high; e += NT) {
        int g = (e < n_low) ? (gc_lo + e) : (hi + (e - n_low));
        int j0 = g * GS;
        #pragma unroll
        for (int k = 0; k < GS; k++) {
            int j = j0 + k;
            int s = 2 * j - mv;
            if (s < 0) s += L; else if (s >= L) s -= L;
            int s1 = s + 1; if (s1 >= L) s1 -= L;
            float p = (xrow[s] + xrow[s1]) * 0.5f
                    + (noise[2 * j] + noise[2 * j + 1]) * 0.02f;
            prow[j] = __float2half_rn(p);
            sum += p; sumsq = fmaf(p, p, sumsq);
        }
    }
    // tail pooled indices (halfL % GS != 0), owned by last chunk
    if (c == CPR - 1) {
        for (int j = ngroups * GS + tid; j < halfL; j += NT) {
            int s = 2 * j - mv;
            if (s < 0) s += L; else if (s >= L) s -= L;
            int s1 = s + 1; if (s1 >= L) s1 -= L;
            float p = (xrow[s] + xrow[s1]) * 0.5f
                    + (noise[2 * j] + noise[2 * j + 1]) * 0.02f;
            prow[j] = __float2half_rn(p);
            sum += p; sumsq = fmaf(p, p, sumsq);
        }
    }

    // ---- hot loop: 8x LDG.128 (x) + 8x LDG.128 (noise,L2) + 2x STG.128 ----
    for (int g = lo + tid; g < hi; g += NT) {
        const int j0 = g * GS;
        const int s0 = 2 * j0 - mv;        // 16B-aligned on fast path
        const int n0 = 2 * j0;             // always 64B-aligned

        float4 xa[8], na[8];
        #pragma unroll
        for (int k = 0; k < 8; k++)
            xa[k] = __ldcs(reinterpret_cast<const float4*>(xrow + s0 + 4 * k));
        #pragma unroll
        for (int k = 0; k < 8; k++)
            na[k] = *reinterpret_cast<const float4*>(noise + n0 + 4 * k);

        float p[GS];
        #pragma unroll
        for (int k = 0; k < 8; k++) {
            p[2 * k]     = (xa[k].x + xa[k].y) * 0.5f + (na[k].x + na[k].y) * 0.02f;
            p[2 * k + 1] = (xa[k].z + xa[k].w) * 0.5f + (na[k].z + na[k].w) * 0.02f;
        }

        uint4 pk0, pk1;
        {
            __half2 h0 = __floats2half2_rn(p[0],  p[1]);
            __half2 h1 = __floats2half2_rn(p[2],  p[3]);
            __half2 h2 = __floats2half2_rn(p[4],  p[5]);
            __half2 h3 = __floats2half2_rn(p[6],  p[7]);
            __half2 h4 = __floats2half2_rn(p[8],  p[9]);
            __half2 h5 = __floats2half2_rn(p[10], p[11]);
            __half2 h6 = __floats2half2_rn(p[12], p[13]);
            __half2 h7 = __floats2half2_rn(p[14], p[15]);
            pk0.x = *reinterpret_cast<unsigned int*>(&h0);
            pk0.y = *reinterpret_cast<unsigned int*>(&h1);
            pk0.z = *reinterpret_cast<unsigned int*>(&h2);
            pk0.w = *reinterpret_cast<unsigned int*>(&h3);
            pk1.x = *reinterpret_cast<unsigned int*>(&h4);
            pk1.y = *reinterpret_cast<unsigned int*>(&h5);
            pk1.z = *reinterpret_cast<unsigned int*>(&h6);
            pk1.w = *reinterpret_cast<unsigned int*>(&h7);
        }
        *reinterpret_cast<uint4*>(prow + j0)     = pk0;
        *reinterpret_cast<uint4*>(prow + j0 + 8) = pk1;

        #pragma unroll
        for (int k = 0; k < GS; k++) {
            sum  += p[k];
            sumsq = fmaf(p[k], p[k], sumsq);
        }
    }

    // ---- deterministic block reduction ----
    __shared__ float s_s[NT / 32], s_q[NT / 32];
    #pragma unroll
    for (int o = 16; o > 0; o >>= 1) {
        sum   += __shfl_down_sync(0xFFFFFFFFu, sum,   o);
        sumsq += __shfl_down_sync(0xFFFFFFFFu, sumsq, o);
    }
    if ((tid & 31) == 0) { s_s[tid >> 5] = sum; s_q[tid >> 5] = sumsq; }
    __syncthreads();
    if (tid == 0) {
        float S = 0.0f, Q = 0.0f;
        #pragma unroll
        for (int w = 0; w < NT / 32; w++) { S += s_s[w]; Q += s_q[w]; }
        g_part[row * CPR + c] = make_float2(S, Q);
    }
}

// Pass 2: fold partials -> mu, 1/sd; fp16 scratch (L2) -> duplicated fp32 out.
__global__ __launch_bounds__(NT)
void pass2_kernel(float* __restrict__ out, int L) {
    const int halfL   = L >> 1;
    const int ngroups = halfL / GS;
    const int gpc     = (ngroups + CPR - 1) / CPR;
    const int row     = blockIdx.x / CPR;
    const int c       = blockIdx.x % CPR;
    const int g_lo    = c * gpc;
    const int g_hi    = min(g_lo + gpc, ngroups);
    const int tid     = threadIdx.x;

    float S = 0.0f, Q = 0.0f;
    #pragma unroll
    for (int k = 0; k < CPR; k++) {
        float2 pp = g_part[row * CPR + k];      // 128 B per row, L2-hot
        S += pp.x; Q += pp.y;
    }
    const float inv_n  = 1.0f / (float)halfL;
    const float mu     = S * inv_n;
    const float inv_sd = rsqrtf(fmaxf(Q * inv_n - mu * mu, 0.0f));

    const __half* __restrict__ prow = g_pool + (size_t)row * (size_t)halfL;
    float*        __restrict__ orow = out + (size_t)row * (size_t)L;

    // hot loop: 2x LDG.128 (scratch) + 8x STG.128 (out, streaming)
    for (int g = g_lo + tid; g < g_hi; g += NT) {
        const int j0 = g * GS;
        uint4 r0 = *reinterpret_cast<const uint4*>(prow + j0);
        uint4 r1 = *reinterpret_cast<const uint4*>(prow + j0 + 8);

        float v[GS];
        {
            float2 f;
            f = __half22float2(*reinterpret_cast<__half2*>(&r0.x)); v[0]=f.x;  v[1]=f.y;
            f = __half22float2(*reinterpret_cast<__half2*>(&r0.y)); v[2]=f.x;  v[3]=f.y;
            f = __half22float2(*reinterpret_cast<__half2*>(&r0.z)); v[4]=f.x;  v[5]=f.y;
            f = __half22float2(*reinterpret_cast<__half2*>(&r0.w)); v[6]=f.x;  v[7]=f.y;
            f = __half22float2(*reinterpret_cast<__half2*>(&r1.x)); v[8]=f.x;  v[9]=f.y;
            f = __half22float2(*reinterpret_cast<__half2*>(&r1.y)); v[10]=f.x; v[11]=f.y;
            f = __half22float2(*reinterpret_cast<__half2*>(&r1.z)); v[12]=f.x; v[13]=f.y;
            f = __half22float2(*reinterpret_cast<__half2*>(&r1.w)); v[14]=f.x; v[15]=f.y;
        }
        #pragma unroll
        for (int k = 0; k < GS; k++) v[k] = (v[k] - mu) * inv_sd;

        float* o = orow + 2 * j0;
        #pragma unroll
        for (int k = 0; k < 8; k++) {
            float4 w = {v[2 * k], v[2 * k], v[2 * k + 1], v[2 * k + 1]};
            __stcs(reinterpret_cast<float4*>(o + 4 * k), w);
        }
    }
    if (c == CPR - 1) {
        for (int j = ngroups * GS + tid; j < halfL; j += NT) {
            float vv = (__half2float(prow[j]) - mu) * inv_sd;
            orow[2 * j]     = vv;
            orow[2 * j + 1] = vv;
        }
    }
}

extern "C" void kernel_launch(void* const* d_in, const int* in_sizes, int n_in,
                              void* d_out, int out_size) {
    const float* x     = (const float*)d_in[0];
    const float* noise = (const float*)d_in[1];
    const int*   move  = (const int*)d_in[2];
    float*       out   = (float*)d_out;

    const int L = in_sizes[1];              // 100000
    const int B = in_sizes[0] / L;          // 512

    pass1_kernel<<<B * CPR, NT>>>(x, noise, move, L);
    pass2_kernel<<<B * CPR, NT>>>(out, L);
}

// round 16
// speedup vs baseline: 1.0490x; 1.0490x over previous
#include <cuda_runtime.h>
#include <cuda_fp16.h>
#include <math.h>

#define MAX_B    512
#define MAX_HALF 50048
#define CPR      16          // chunk CTAs per row
#define NT       256         // threads per CTA
#define GS       16          // pooled values per group (one hot iteration)

// Pooled rows scratch in fp16 (51 MB) — written pass1, read pass2; L2-friendly.
__device__ __half g_pool[(size_t)MAX_B * MAX_HALF];
// Per-(row,chunk) partial moments {sum, sumsq}
__device__ float2 g_part[MAX_B * CPR];

// Pass 1: stream x (ldcs) + noise (L2-resident), pooled fp16 -> g_pool,
// partial (sum,sumsq) per chunk -> g_part.  16 pooled per hot iteration.
__global__ __launch_bounds__(NT)
void pass1_kernel(const float* __restrict__ x,
                  const float* __restrict__ noise,
                  const int*   __restrict__ move_p,
                  int L) {
    const int halfL   = L >> 1;
    const int ngroups = halfL / GS;
    const int gpc     = (ngroups + CPR - 1) / CPR;
    const int row     = blockIdx.x / CPR;
    const int c       = blockIdx.x % CPR;
    const int gc_lo   = c * gpc;
    const int gc_hi   = min(gc_lo + gpc, ngroups);
    const int tid     = threadIdx.x;

    const float* __restrict__ xrow = x + (size_t)row * (size_t)L;
    __half*      __restrict__ prow = g_pool + (size_t)row * (size_t)halfL;

    int mv = __ldg(move_p);
    mv %= L; if (mv < 0) mv += L;

    // Fast-path interval in group space: s0 = 2*GS*g - mv needs
    // s0 >= 0, s0 + 2*GS - 1 < L, and 16B alignment (mv % 4 == 0).
    int fl, fh;
    if ((mv & 3) == 0) {
        fl = (mv + 2 * GS - 1) / (2 * GS);        if (fl > ngroups) fl = ngroups;
        fh = (L + mv - 2 * GS) / (2 * GS) + 1;    if (fh > ngroups) fh = ngroups;
        if (fh < fl) fh = fl;
    } else { fl = 0; fh = 0; }

    int lo = max(gc_lo, fl); if (lo > gc_hi) lo = gc_hi;
    int hi = min(gc_hi, fh); if (hi < lo)    hi = lo;

    float sum = 0.0f, sumsq = 0.0f;

    // ---- scalar edge groups (wrap region) ----
    const int n_low = lo - gc_lo, n_high = gc_hi - hi;
    for (int e = tid; e < n_low + n_high; e += NT) {
        int g = (e < n_low) ? (gc_lo + e) : (hi + (e - n_low));
        int j0 = g * GS;
        #pragma unroll
        for (int k = 0; k < GS; k++) {
            int j = j0 + k;
            int s = 2 * j - mv;
            if (s < 0) s += L; else if (s >= L) s -= L;
            int s1 = s + 1; if (s1 >= L) s1 -= L;
            float p = (xrow[s] + xrow[s1]) * 0.5f
                    + (noise[2 * j] + noise[2 * j + 1]) * 0.02f;
            prow[j] = __float2half_rn(p);
            sum += p; sumsq = fmaf(p, p, sumsq);
        }
    }
    // tail pooled indices (halfL % GS != 0), owned by last chunk
    if (c == CPR - 1) {
        for (int j = ngroups * GS + tid; j < halfL; j += NT) {
            int s = 2 * j - mv;
            if (s < 0) s += L; else if (s >= L) s -= L;
            int s1 = s + 1; if (s1 >= L) s1 -= L;
            float p = (xrow[s] + xrow[s1]) * 0.5f
                    + (noise[2 * j] + noise[2 * j + 1]) * 0.02f;
            prow[j] = __float2half_rn(p);
            sum += p; sumsq = fmaf(p, p, sumsq);
        }
    }

    // ---- hot loop: 8x LDG.128 (x) + 8x LDG.128 (noise,L2) + 2x STG.128 ----
    for (int g = lo + tid; g < hi; g += NT) {
        const int j0 = g * GS;
        const int s0 = 2 * j0 - mv;        // 16B-aligned on fast path
        const int n0 = 2 * j0;             // always 64B-aligned

        float4 xa[8], na[8];
        #pragma unroll
        for (int k = 0; k < 8; k++)
            xa[k] = __ldcs(reinterpret_cast<const float4*>(xrow + s0 + 4 * k));
        #pragma unroll
        for (int k = 0; k < 8; k++)
            na[k] = *reinterpret_cast<const float4*>(noise + n0 + 4 * k);

        float p[GS];
        #pragma unroll
        for (int k = 0; k < 8; k++) {
            p[2 * k]     = (xa[k].x + xa[k].y) * 0.5f + (na[k].x + na[k].y) * 0.02f;
            p[2 * k + 1] = (xa[k].z + xa[k].w) * 0.5f + (na[k].z + na[k].w) * 0.02f;
        }

        uint4 pk0, pk1;
        {
            __half2 h0 = __floats2half2_rn(p[0],  p[1]);
            __half2 h1 = __floats2half2_rn(p[2],  p[3]);
            __half2 h2 = __floats2half2_rn(p[4],  p[5]);
            __half2 h3 = __floats2half2_rn(p[6],  p[7]);
            __half2 h4 = __floats2half2_rn(p[8],  p[9]);
            __half2 h5 = __floats2half2_rn(p[10], p[11]);
            __half2 h6 = __floats2half2_rn(p[12], p[13]);
            __half2 h7 = __floats2half2_rn(p[14], p[15]);
            pk0.x = *reinterpret_cast<unsigned int*>(&h0);
            pk0.y = *reinterpret_cast<unsigned int*>(&h1);
            pk0.z = *reinterpret_cast<unsigned int*>(&h2);
            pk0.w = *reinterpret_cast<unsigned int*>(&h3);
            pk1.x = *reinterpret_cast<unsigned int*>(&h4);
            pk1.y = *reinterpret_cast<unsigned int*>(&h5);
            pk1.z = *reinterpret_cast<unsigned int*>(&h6);
            pk1.w = *reinterpret_cast<unsigned int*>(&h7);
        }
        *reinterpret_cast<uint4*>(prow + j0)     = pk0;
        *reinterpret_cast<uint4*>(prow + j0 + 8) = pk1;

        #pragma unroll
        for (int k = 0; k < GS; k++) {
            sum  += p[k];
            sumsq = fmaf(p[k], p[k], sumsq);
        }
    }

    // ---- deterministic block reduction ----
    __shared__ float s_s[NT / 32], s_q[NT / 32];
    #pragma unroll
    for (int o = 16; o > 0; o >>= 1) {
        sum   += __shfl_down_sync(0xFFFFFFFFu, sum,   o);
        sumsq += __shfl_down_sync(0xFFFFFFFFu, sumsq, o);
    }
    if ((tid & 31) == 0) { s_s[tid >> 5] = sum; s_q[tid >> 5] = sumsq; }
    __syncthreads();
    if (tid == 0) {
        float S = 0.0f, Q = 0.0f;
        #pragma unroll
        for (int w = 0; w < NT / 32; w++) { S += s_s[w]; Q += s_q[w]; }
        g_part[row * CPR + c] = make_float2(S, Q);
    }
}

// Pass 2: fold partials -> mu, 1/sd; fp16 scratch (L2) -> duplicated fp32 out.
__global__ __launch_bounds__(NT)
void pass2_kernel(float* __restrict__ out, int L) {
    const int halfL   = L >> 1;
    const int ngroups = halfL / GS;
    const int gpc     = (ngroups + CPR - 1) / CPR;
    const int row     = blockIdx.x / CPR;
    const int c       = blockIdx.x % CPR;
    const int g_lo    = c * gpc;
    const int g_hi    = min(g_lo + gpc, ngroups);
    const int tid     = threadIdx.x;

    float S = 0.0f, Q = 0.0f;
    #pragma unroll
    for (int k = 0; k < CPR; k++) {
        float2 pp = g_part[row * CPR + k];      // 128 B per row, L2-hot
        S += pp.x; Q += pp.y;
    }
    const float inv_n  = 1.0f / (float)halfL;
    const float mu     = S * inv_n;
    const float inv_sd = rsqrtf(fmaxf(Q * inv_n - mu * mu, 0.0f));

    const __half* __restrict__ prow = g_pool + (size_t)row * (size_t)halfL;
    float*        __restrict__ orow = out + (size_t)row * (size_t)L;

    // hot loop: 2x LDG.128 (scratch) + 8x STG.128 (out, streaming)
    for (int g = g_lo + tid; g < g_hi; g += NT) {
        const int j0 = g * GS;
        uint4 r0 = *reinterpret_cast<const uint4*>(prow + j0);
        uint4 r1 = *reinterpret_cast<const uint4*>(prow + j0 + 8);

        float v[GS];
        {
            float2 f;
            f = __half22float2(*reinterpret_cast<__half2*>(&r0.x)); v[0]=f.x;  v[1]=f.y;
            f = __half22float2(*reinterpret_cast<__half2*>(&r0.y)); v[2]=f.x;  v[3]=f.y;
            f = __half22float2(*reinterpret_cast<__half2*>(&r0.z)); v[4]=f.x;  v[5]=f.y;
            f = __half22float2(*reinterpret_cast<__half2*>(&r0.w)); v[6]=f.x;  v[7]=f.y;
            f = __half22float2(*reinterpret_cast<__half2*>(&r1.x)); v[8]=f.x;  v[9]=f.y;
            f = __half22float2(*reinterpret_cast<__half2*>(&r1.y)); v[10]=f.x; v[11]=f.y;
            f = __half22float2(*reinterpret_cast<__half2*>(&r1.z)); v[12]=f.x; v[13]=f.y;
            f = __half22float2(*reinterpret_cast<__half2*>(&r1.w)); v[14]=f.x; v[15]=f.y;
        }
        #pragma unroll
        for (int k = 0; k < GS; k++) v[k] = (v[k] - mu) * inv_sd;

        float* o = orow + 2 * j0;
        #pragma unroll
        for (int k = 0; k < 8; k++) {
            float4 w = {v[2 * k], v[2 * k], v[2 * k + 1], v[2 * k + 1]};
            __stcs(reinterpret_cast<float4*>(o + 4 * k), w);
        }
    }
    if (c == CPR - 1) {
        for (int j = ngroups * GS + tid; j < halfL; j += NT) {
            float vv = (__half2float(prow[j]) - mu) * inv_sd;
            orow[2 * j]     = vv;
            orow[2 * j + 1] = vv;
        }
    }
}

extern "C" void kernel_launch(void* const* d_in, const int* in_sizes, int n_in,
                              void* d_out, int out_size) {
    const float* x     = (const float*)d_in[0];
    const float* noise = (const float*)d_in[1];
    const int*   move  = (const int*)d_in[2];
    float*       out   = (float*)d_out;

    const int L = in_sizes[1];              // 100000
    const int B = in_sizes[0] / L;          // 512

    pass1_kernel<<<B * CPR, NT>>>(x, noise, move, L);
    pass2_kernel<<<B * CPR, NT>>>(out, L);
}

// round 17
// speedup vs baseline: 1.9184x; 1.8289x over previous
#include <cuda_runtime.h>
#include <cuda_fp16.h>
#include <math.h>

#define MAX_B    512
#define MAX_HALF 50048
#define CPR      16          // chunk CTAs per row (pass1)
#define NT       256         // threads per CTA

// Row-invariant pooled noise: (noise[2j]+noise[2j+1])*STD/2 (STD=0.04)
__device__ float  g_npool[MAX_HALF];
// Pooled rows scratch in fp16 (51 MB) — written pass1, read pass2.
__device__ __half g_pool[(size_t)MAX_B * MAX_HALF];
// Per-(row,chunk) partial moments {sum, sumsq}
__device__ float2 g_part[MAX_B * CPR];
// Per-row {mu, inv_sd}
__device__ float2 g_stats[MAX_B];

__global__ void npool_kernel(const float* __restrict__ noise, int halfL) {
    int j = blockIdx.x * blockDim.x + threadIdx.x;
    if (j < halfL)
        g_npool[j] = (noise[2 * j] + noise[2 * j + 1]) * 0.02f;
}

// Pass 1 (R12-proven shape): stream x (ldcs), pooled fp16 -> g_pool,
// partial (sum,sumsq) per chunk -> g_part. 8 pooled per hot iteration;
// scratch store is 16 B/lane -> perfectly lane-contiguous STG.128.
__global__ __launch_bounds__(NT)
void pass1_kernel(const float* __restrict__ x,
                  const int*   __restrict__ move_p,
                  int L) {
    const int halfL   = L >> 1;
    const int ngroups = halfL >> 3;
    const int gpc     = (ngroups + CPR - 1) / CPR;
    const int row     = blockIdx.x / CPR;
    const int c       = blockIdx.x % CPR;
    const int gc_lo   = c * gpc;
    const int gc_hi   = min(gc_lo + gpc, ngroups);
    const int tid     = threadIdx.x;

    const float* __restrict__ xrow = x + (size_t)row * (size_t)L;
    __half*      __restrict__ prow = g_pool + (size_t)row * (size_t)halfL;

    int mv = __ldg(move_p);
    mv %= L; if (mv < 0) mv += L;

    int fl, fh;
    if ((mv & 3) == 0) {
        fl = (mv + 15) >> 4;           if (fl > ngroups) fl = ngroups;
        fh = (L + mv - 16) / 16 + 1;   if (fh > ngroups) fh = ngroups;
        if (fh < fl) fh = fl;
    } else { fl = 0; fh = 0; }

    int lo = max(gc_lo, fl); if (lo > gc_hi) lo = gc_hi;
    int hi = min(gc_hi, fh); if (hi < lo)    hi = lo;

    float sum = 0.0f, sumsq = 0.0f;

    // scalar edge groups (wrap region)
    const int n_low = lo - gc_lo, n_high = gc_hi - hi;
    for (int e = tid; e < n_low + n_high; e += NT) {
        int g = (e < n_low) ? (gc_lo + e) : (hi + (e - n_low));
        int j0 = g << 3;
        #pragma unroll
        for (int k = 0; k < 8; k++) {
            int j = j0 + k;
            int s = 2 * j - mv;
            if (s < 0) s += L; else if (s >= L) s -= L;
            int s1 = s + 1; if (s1 >= L) s1 -= L;
            float p = (xrow[s] + xrow[s1]) * 0.5f + g_npool[j];
            prow[j] = __float2half_rn(p);
            sum += p; sumsq = fmaf(p, p, sumsq);
        }
    }
    if (c == CPR - 1) {  // tail pooled indices (halfL % 8 != 0)
        for (int j = (ngroups << 3) + tid; j < halfL; j += NT) {
            int s = 2 * j - mv;
            if (s < 0) s += L; else if (s >= L) s -= L;
            int s1 = s + 1; if (s1 >= L) s1 -= L;
            float p = (xrow[s] + xrow[s1]) * 0.5f + g_npool[j];
            prow[j] = __float2half_rn(p);
            sum += p; sumsq = fmaf(p, p, sumsq);
        }
    }

    // hot loop: 4x LDG.128 (x) + 2x LDG.128 (npool,L2) + 1x contiguous STG.128
    for (int g = lo + tid; g < hi; g += NT) {
        const int j0 = g << 3;
        const int s0 = (g << 4) - mv;
        float4 a = __ldcs(reinterpret_cast<const float4*>(xrow + s0));
        float4 b = __ldcs(reinterpret_cast<const float4*>(xrow + s0 + 4));
        float4 d = __ldcs(reinterpret_cast<const float4*>(xrow + s0 + 8));
        float4 e = __ldcs(reinterpret_cast<const float4*>(xrow + s0 + 12));
        float4 n0 = *reinterpret_cast<const float4*>(g_npool + j0);
        float4 n1 = *reinterpret_cast<const float4*>(g_npool + j0 + 4);

        float p0 = (a.x + a.y) * 0.5f + n0.x;
        float p1 = (a.z + a.w) * 0.5f + n0.y;
        float p2 = (b.x + b.y) * 0.5f + n0.z;
        float p3 = (b.z + b.w) * 0.5f + n0.w;
        float p4 = (d.x + d.y) * 0.5f + n1.x;
        float p5 = (d.z + d.w) * 0.5f + n1.y;
        float p6 = (e.x + e.y) * 0.5f + n1.z;
        float p7 = (e.z + e.w) * 0.5f + n1.w;

        __half2 h0 = __floats2half2_rn(p0, p1);
        __half2 h1 = __floats2half2_rn(p2, p3);
        __half2 h2 = __floats2half2_rn(p4, p5);
        __half2 h3 = __floats2half2_rn(p6, p7);
        uint4 packed;
        packed.x = *reinterpret_cast<unsigned int*>(&h0);
        packed.y = *reinterpret_cast<unsigned int*>(&h1);
        packed.z = *reinterpret_cast<unsigned int*>(&h2);
        packed.w = *reinterpret_cast<unsigned int*>(&h3);
        *reinterpret_cast<uint4*>(prow + j0) = packed;

        sum  += ((p0 + p1) + (p2 + p3)) + ((p4 + p5) + (p6 + p7));
        sumsq = fmaf(p0, p0, sumsq); sumsq = fmaf(p1, p1, sumsq);
        sumsq = fmaf(p2, p2, sumsq); sumsq = fmaf(p3, p3, sumsq);
        sumsq = fmaf(p4, p4, sumsq); sumsq = fmaf(p5, p5, sumsq);
        sumsq = fmaf(p6, p6, sumsq); sumsq = fmaf(p7, p7, sumsq);
    }

    __shared__ float s_s[NT / 32], s_q[NT / 32];
    #pragma unroll
    for (int o = 16; o > 0; o >>= 1) {
        sum   += __shfl_down_sync(0xFFFFFFFFu, sum,   o);
        sumsq += __shfl_down_sync(0xFFFFFFFFu, sumsq, o);
    }
    if ((tid & 31) == 0) { s_s[tid >> 5] = sum; s_q[tid >> 5] = sumsq; }
    __syncthreads();
    if (tid == 0) {
        float S = 0.0f, Q = 0.0f;
        #pragma unroll
        for (int w = 0; w < NT / 32; w++) { S += s_s[w]; Q += s_q[w]; }
        g_part[row * CPR + c] = make_float2(S, Q);
    }
}

// Tiny stats fold: one thread per row.
__global__ void stats_kernel(int B, int halfL) {
    int r = blockIdx.x * blockDim.x + threadIdx.x;
    if (r >= B) return;
    float S = 0.0f, Q = 0.0f;
    #pragma unroll
    for (int k = 0; k < CPR; k++) {
        float2 p = g_part[r * CPR + k];
        S += p.x; Q += p.y;
    }
    float inv_n = 1.0f / (float)halfL;
    float mu    = S * inv_n;
    float var   = fmaxf(Q * inv_n - mu * mu, 0.0f);
    g_stats[r] = make_float2(mu, rsqrtf(var));
}

// Pass 2: one output float4 per thread-slot, lanes contiguous.
// Per iter: LDG.32 (__half2 scratch, contiguous 128 B/warp)
//         + STG.128 (out, contiguous 512 B/warp, streaming).
__global__ __launch_bounds__(NT)
void pass2_kernel(float* __restrict__ out, int L, int B) {
    const int halfL = L >> 1;
    const int q     = L >> 2;                       // float4s per row (L%4==0)
    const long long total  = (long long)B * q;
    const long long stride = (long long)gridDim.x * NT;

    for (long long idx = (long long)blockIdx.x * NT + threadIdx.x;
         idx < total; idx += stride) {
        int row = (int)(idx / q);
        int i   = (int)(idx - (long long)row * q);
        float2 st = g_stats[row];                   // warp-uniform, L2-hot
        __half2 h = *reinterpret_cast<const __half2*>(
                        g_pool + (size_t)row * halfL + 2 * i);
        float2 f = __half22float2(h);
        float v0 = (f.x - st.x) * st.y;
        float v1 = (f.y - st.x) * st.y;
        float4 w = {v0, v0, v1, v1};
        __stcs(reinterpret_cast<float4*>(out) + idx, w);
    }
}

// Generic scalar fallback for L % 4 != 0 (not hit for L=100000).
__global__ void pass2_scalar_kernel(float* __restrict__ out, int L, int B) {
    const int halfL = L >> 1;
    long long total = (long long)B * L;
    long long stride = (long long)gridDim.x * blockDim.x;
    for (long long t = (long long)blockIdx.x * blockDim.x + threadIdx.x;
         t < total; t += stride) {
        int row = (int)(t / L);
        int i   = (int)(t - (long long)row * L);
        float2 st = g_stats[row];
        float p = __half2float(g_pool[(size_t)row * halfL + (i >> 1)]);
        out[t] = (p - st.x) * st.y;
    }
}

extern "C" void kernel_launch(void* const* d_in, const int* in_sizes, int n_in,
                              void* d_out, int out_size) {
    const float* x     = (const float*)d_in[0];
    const float* noise = (const float*)d_in[1];
    const int*   move  = (const int*)d_in[2];
    float*       out   = (float*)d_out;

    const int L     = in_sizes[1];          // 100000
    const int B     = in_sizes[0] / L;      // 512
    const int halfL = L / 2;

    npool_kernel<<<(halfL + 255) / 256, 256>>>(noise, halfL);
    pass1_kernel<<<B * CPR, NT>>>(x, move, L);
    stats_kernel<<<(B + 255) / 256, 256>>>(B, halfL);

    if ((L & 3) == 0) {
        long long total = (long long)B * (L >> 2);   // 12.8M float4s
        int iters_per_thread = 4;
        long long ctas = (total + (long long)NT * iters_per_thread - 1)
                         / ((long long)NT * iters_per_thread);
        pass2_kernel<<<(int)ctas, NT>>>(out, L, B);
    } else {
        pass2_scalar_kernel<<<8192, NT>>>(out, L, B);
    }
}